// round 6
// baseline (speedup 1.0000x reference)
#include <cuda_runtime.h>

// Kalman: NCV(4) + 128 static sensor biases, T=4096. Exact decomposition
// (validated rounds 2-4). Round 5: f32x2-packed warp-specialized pipelines
// + Newton reciprocal (hybrid: exact rcp in first window) + W-trick, to
// lower both the fma-pipe issue floor and the loop-carried RAW chain of
// the Riccati warp.

#define T_STEPS 4096
#define OBS 128
#define WIN 64
#define NWIN (T_STEPS / WIN)

typedef unsigned long long u64;

__device__ float g_ybar[2 * T_STEPS];

__global__ void ybar_kernel(const float4* __restrict__ obs4) {
    int gw   = (blockIdx.x * blockDim.x + threadIdx.x) >> 5;
    int lane = threadIdx.x & 31;
    int nw   = (gridDim.x * blockDim.x) >> 5;
    for (int t = gw; t < T_STEPS; t += nw) {
        float4 v = obs4[t * 32 + lane];
        float s = (v.x + v.y) + (v.z + v.w);
        #pragma unroll
        for (int m = 8; m; m >>= 1)
            s += __shfl_xor_sync(0xffffffffu, s, m);
        s *= 0.015625f;
        if (lane == 0)  g_ybar[2 * t]     = s;
        if (lane == 16) g_ybar[2 * t + 1] = s;
    }
}

__device__ __forceinline__ float frcp(float x) {
    float r;
    asm("rcp.approx.f32 %0, %1;" : "=f"(r) : "f"(x));
    return r;
}
__device__ __forceinline__ u64 pk2(float lo, float hi) {
    u64 d;
    asm("mov.b64 %0, {%1, %2};" : "=l"(d)
        : "r"(__float_as_uint(lo)), "r"(__float_as_uint(hi)));
    return d;
}
__device__ __forceinline__ void unpk2(u64 v, float& lo, float& hi) {
    unsigned a, b;
    asm("mov.b64 {%0, %1}, %2;" : "=r"(a), "=r"(b) : "l"(v));
    lo = __uint_as_float(a); hi = __uint_as_float(b);
}
__device__ __forceinline__ u64 fma2(u64 a, u64 b, u64 c) {
    u64 d;
    asm("fma.rn.f32x2 %0, %1, %2, %3;" : "=l"(d) : "l"(a), "l"(b), "l"(c));
    return d;
}
__device__ __forceinline__ u64 add2(u64 a, u64 b) {
    u64 d;
    asm("add.rn.f32x2 %0, %1, %2;" : "=l"(d) : "l"(a), "l"(b));
    return d;
}
__device__ __forceinline__ u64 mul2(u64 a, u64 b) {
    u64 d;
    asm("mul.rn.f32x2 %0, %1, %2;" : "=l"(d) : "l"(a), "l"(b));
    return d;
}
__device__ __forceinline__ float fneg(float x) {
    return __uint_as_float(__float_as_uint(x) ^ 0x80000000u);
}

// One Riccati step. FIRST: exact rcp (transient window). Else Newton from
// carried nis (negated reciprocal of Sv).
template <bool FIRST>
__device__ __forceinline__ void ricc_step(
    float& a, float& d, float& c, float& E, float& F, float& G, float& nis,
    float q1s, float q2s, float q3s, float R64s,
    bool do_store, ulonglong2* gout)
{
    float dc = d + c;
    float s1 = fmaf(2.0f, d, a);
    float cq = c + q3s;
    float ap = s1 + cq;
    float dp = dc + q2s;
    float cp = c + q1s;
    float Ep = E + F;
    float GR = G + R64s;
    float W  = fmaf(2.0f, Ep, GR);
    float Sv = ap + W;
    if (FIRST) {
        nis = fneg(frcp(Sv));
    } else {
        float tt = fmaf(Sv, nis, 2.0f);
        nis = nis * tt;
    }
    float u1 = ap + Ep;
    float u2 = dp + F;
    float u3 = Ep + G;
    float nk3 = u3 * nis;
    u64 u12  = pk2(u1, u2);
    u64 niss = pk2(nis, nis);
    u64 nk12 = mul2(u12, niss);          // (-k1, -k2)
    float nk1, nk2;
    unpk2(nk12, nk1, nk2);
    u64 AD = fma2(u12, pk2(nk1, nk1), pk2(ap, dp));   // (a', d')
    u64 EF = fma2(nk12, pk2(u3, u3), pk2(Ep, F));     // (E', F')
    u64 CG = fma2(pk2(nk2, nk3), pk2(u2, u3), pk2(cp, G)); // (c', G')
    unpk2(AD, a, d);
    unpk2(EF, E, F);
    unpk2(CG, c, G);
    if (do_store) {
        ulonglong2 e;
        e.x = nk12;
        e.y = pk2(nk3, nis);
        *gout = e;
    }
}

// dynamic smem layout (floats):
//   [0)      float2 yb[4096]       8192
//   [8192)   float2 kapia[4096]    8192
//   [16384)  float  isv[4096]      4096
//   [20480)  ulonglong2 g[2*WIN]    512 floats (2KB)
//   [20992)  float  red[64]
//   [21056)  float  ld[256]
//   [21312)  float  fin[16]
#define SMEM_FLOATS 21328
#define SMEM_BYTES  (SMEM_FLOATS * 4)

__global__ void __launch_bounds__(256, 1) kalman_kernel(
    const float* __restrict__ obs,
    const float* __restrict__ lbs,
    const float* __restrict__ lon,
    const float* __restrict__ ltn,
    float* __restrict__ out)
{
    extern __shared__ float smem[];
    float2*     s_yb  = (float2*)smem;
    float2*     s_ki  = (float2*)(smem + 8192);
    float*      s_isv = smem + 16384;
    ulonglong2* s_g   = (ulonglong2*)(smem + 20480);
    float*      s_red = smem + 20992;
    float*      s_ld  = smem + 21056;
    float*      s_fin = smem + 21312;

    const int tid  = threadIdx.x;
    const int wid  = tid >> 5;
    const int lane = tid & 31;

    const float R  = expf(2.0f * lon[0]);
    const float q  = expf(2.0f * ltn[0]);
    const float g0 = expf(2.0f * lbs[0]);
    const float q1 = q, q2 = 0.5f * q, q3 = q * (1.0f / 3.0f);
    const float R64 = R * 0.015625f;
    const float iR  = frcp(R);

    // ---- prologue: stage ybar, build (kap, ia) table ----
    {
        const float4* src = (const float4*)g_ybar;
        float4*       dst = (float4*)s_yb;
        #pragma unroll
        for (int i = tid; i < 2 * T_STEPS / 4; i += 256) dst[i] = src[i];
    }
    for (int t = tid; t < T_STEPS; t += 256) {
        float den0 = fmaf((float)t, g0, R);
        float den1 = den0 + g0;
        float u    = frcp(den1);
        float kap  = g0 * u;
        float ia   = den0 * u * iR;     // 1/alpha_t
        s_ki[t] = make_float2(kap, ia);
    }
    __syncthreads();

    if (wid == 0) {
        // =========== Riccati gain chain ===========
        float a = 100.0f, c = 100.0f, d = 0.0f;
        float E = 0.0f, F = 0.0f, G = g0 * 0.015625f;
        float nis = -1.0f;
        const bool st = (lane == 0);
        for (int w = 0; w <= NWIN; ++w) {
            if (w == 0) {
                ulonglong2* gb = s_g;
                #pragma unroll 8
                for (int j = 0; j < WIN; ++j)
                    ricc_step<true>(a, d, c, E, F, G, nis,
                                    q1, q2, q3, R64, st, gb + j);
            } else if (w < NWIN) {
                ulonglong2* gb = s_g + (w & 1) * WIN;
                #pragma unroll 8
                for (int j = 0; j < WIN; ++j)
                    ricc_step<false>(a, d, c, E, F, G, nis,
                                     q1, q2, q3, R64, st, gb + j);
            }
            asm volatile("bar.sync 1, 64;" ::: "memory");
        }
        if (lane == 0) {
            s_fin[1] = a; s_fin[2] = d; s_fin[3] = c;
        }
    } else if (wid == 1) {
        // =========== mean / loglik chain (lags one window) ===========
        const u64 NEG1 = pk2(-1.0f, -1.0f);
        u64 m2 = 0, V2 = 0, mV2 = 0, PV2 = 0, Pn2 = 0, llq2 = 0;
        for (int w = 0; w <= NWIN; ++w) {
            if (w > 0) {
                const ulonglong2* gb = s_g + ((w - 1) & 1) * WIN;
                const int tb = (w - 1) * WIN;
                const u64* ybp = (const u64*)(s_yb + tb);
                float* isvp = s_isv + tb;
                #pragma unroll 8
                for (int j = 0; j < WIN; ++j) {
                    ulonglong2 e = gb[j];
                    float nk1, nk2, nk3, nis;
                    unpk2(e.x, nk1, nk2);
                    unpk2(e.y, nk3, nis);
                    float k12n = nk1 + nk2;
                    float kmn  = k12n + nk3;
                    float k2v  = fneg(nk2);
                    float k12  = fneg(k12n);
                    float km   = fneg(kmn);
                    float is   = fneg(nis);
                    u64 yb2  = ybp[j];
                    u64 Ib   = fma2(m2, NEG1, yb2);
                    u64 vu   = fma2(pk2(k2v, k2v), Ib, V2);
                    u64 mn   = fma2(pk2(km, km),  Ib, mV2);
                    Pn2      = fma2(pk2(k12, k12), Ib, PV2);
                    mV2 = add2(mn, vu);
                    PV2 = add2(Pn2, vu);
                    m2 = mn;  V2 = vu;
                    u64 ss = mul2(Ib, Ib);
                    llq2 = fma2(ss, pk2(is, is), llq2);
                    if (lane == 0) isvp[j] = is;
                }
            }
            asm volatile("bar.sync 1, 64;" ::: "memory");
        }
        if (lane == 0) {
            float l0, l1, P0, P1, V0, V1;
            unpk2(llq2, l0, l1);
            unpk2(Pn2, P0, P1);
            unpk2(V2, V0, V1);
            s_fin[4] = l0 + l1;
            s_fin[5] = P0 - V0;  s_fin[6] = P1 - V1;   // posterior pos
            s_fin[7] = V0;       s_fin[8] = V1;         // posterior vel
        }
    } else if (wid < 4) {
        // =========== sensor bias chains (2 per thread, packed) ===========
        const int sid = tid - 64;                 // 0..63
        const float* yp0 = obs + sid;
        const float* yp1 = obs + sid + 64;
        const u64 NEG1 = pk2(-1.0f, -1.0f);
        u64 d2 = 0, acc2 = 0;
        const u64* ybp = (const u64*)s_yb;
        float y0r[8], y1r[8];
        #pragma unroll
        for (int j = 0; j < 8; ++j) {
            y0r[j] = yp0[j * OBS];
            y1r[j] = yp1[j * OBS];
        }
        for (int t0 = 0; t0 < T_STEPS; t0 += 8) {
            #pragma unroll
            for (int j = 0; j < 8; ++j) {
                int t = t0 + j;
                u64 yb2 = ybp[t];
                float2 ki = s_ki[t];
                u64 y2  = pk2(y0r[j], y1r[j]);
                u64 s   = add2(yb2, d2);           // yb + d
                u64 rt2 = fma2(s, NEG1, y2);       // y - yb - d
                d2   = fma2(pk2(ki.x, ki.x), rt2, d2);
                u64 sq = mul2(rt2, rt2);
                acc2 = fma2(sq, pk2(ki.y, ki.y), acc2);
                int pf = t + 8; if (pf > T_STEPS - 1) pf = T_STEPS - 1;
                y0r[j] = yp0[pf * OBS];
                y1r[j] = yp1[pf * OBS];
            }
        }
        float a0, a1;
        unpk2(acc2, a0, a1);
        s_red[sid] = a0 + a1;
    }
    __syncthreads();

    // deferred logdet: ldS = sum_t log2(Sv_t) = -sum_t log2(iSv_t)
    {
        float ls = 0.0f;
        for (int t = tid; t < T_STEPS; t += 256)
            ls += __log2f(s_isv[t]);
        s_ld[tid] = ls;
    }
    __syncthreads();

    if (tid == 0) {
        float atot = 0.0f;
        #pragma unroll 8
        for (int i = 0; i < 64; ++i) atot += s_red[i];
        float lsum = 0.0f;
        #pragma unroll 8
        for (int i = 0; i < 256; ++i) lsum += s_ld[i];
        double ldS = -(double)lsum;
        double llq = (double)s_fin[4];
        double ldA = (double)(T_STEPS - 1) * log2((double)R)
                   + log2((double)R + (double)T_STEPS * (double)g0);
        double ld  = 63.0 * ldA + ldS + 6.0 * (double)T_STEPS;
        const double LN2    = 0.6931471805599453094;
        const double LOG2PI = 1.8378770664093454836;
        double quad = 0.5 * ((double)atot + llq);
        double logp = -quad - ld * LN2 - 64.0 * (double)T_STEPS * LOG2PI;
        out[0] = (float)logp;
        out[1] = s_fin[5];  out[2] = s_fin[6];
        out[3] = s_fin[7];  out[4] = s_fin[8];
        float a = s_fin[1], d = s_fin[2], c = s_fin[3];
        out[5]  = a;   out[6]  = 0.f; out[7]  = d;   out[8]  = 0.f;
        out[9]  = 0.f; out[10] = a;   out[11] = 0.f; out[12] = d;
        out[13] = d;   out[14] = 0.f; out[15] = c;   out[16] = 0.f;
        out[17] = 0.f; out[18] = d;   out[19] = 0.f; out[20] = c;
    }
}

extern "C" void kernel_launch(void* const* d_in, const int* in_sizes, int n_in,
                              void* d_out, int out_size) {
    const float* obs = (const float*)d_in[0];
    const float* lbs = (const float*)d_in[1];
    const float* lon = (const float*)d_in[2];
    const float* ltn = (const float*)d_in[3];
    float* out = (float*)d_out;
    (void)in_sizes; (void)n_in; (void)out_size;

    static bool attr_set = false;
    if (!attr_set) {
        cudaFuncSetAttribute(kalman_kernel,
                             cudaFuncAttributeMaxDynamicSharedMemorySize,
                             SMEM_BYTES);
        attr_set = true;
    }
    ybar_kernel<<<64, 256>>>((const float4*)obs);
    kalman_kernel<<<1, 256, SMEM_BYTES>>>(obs, lbs, lon, ltn, out);
}

// round 7
// speedup vs baseline: 1.9153x; 1.9153x over previous
#include <cuda_runtime.h>

// Kalman: NCV(4) + 128 static sensor biases, T=4096.
// Round 6 (reissued): shrink the serial region to t<1024.
//  - Serial Riccati (warp0) + serial mean chain (warp1) for t<1024, pipelined
//    via named barrier 1 (scheme validated rounds 3-5).
//  - Gains for t>=1024 via quadratic Lagrange extrapolation in x=1/tau
//    (nodes tau=512/768/1024): static-bias mode gives covariance analytic in
//    1/tau; NCV transient geometric, dead long before tau=512.
//  - Mean chain t>=1024 via blocked affine scan (48 chunks x 64 steps).
//  - Sensor bias chains are a scaled prefix sum -> parallel prepass kernel.

#define T_STEPS 4096
#define OBS 128
#define T1 1024
#define WIN 64
#define NW1 (T1 / WIN)
#define CH ((T_STEPS - T1) / WIN)

__device__ float g_ybar[2 * T_STEPS];
__device__ float g_itg[T_STEPS];
__device__ float g_iaT[T_STEPS];
__device__ float g_acc[OBS];

__device__ __forceinline__ float frcp(float x) {
    float r;
    asm("rcp.approx.f32 %0, %1;" : "=f"(r) : "f"(x));
    return r;
}

// ---------- K1: per-step obs group means + scalar tables ----------
__global__ void prep_kernel(const float4* __restrict__ obs4,
                            const float* __restrict__ lbs,
                            const float* __restrict__ lon) {
    int gtid = blockIdx.x * blockDim.x + threadIdx.x;
    int gw = gtid >> 5, lane = gtid & 31;
    int nw = (gridDim.x * blockDim.x) >> 5;
    for (int t = gw; t < T_STEPS; t += nw) {
        float4 v = obs4[t * 32 + lane];
        // lanes 0..15: obs 0..63 (x group); lanes 16..31: obs 64..127 (y)
        float s = (v.x + v.y) + (v.z + v.w);
        #pragma unroll
        for (int m = 8; m; m >>= 1)
            s += __shfl_xor_sync(0xffffffffu, s, m);
        s *= 0.015625f;
        if (lane == 0)  g_ybar[2 * t]     = s;
        if (lane == 16) g_ybar[2 * t + 1] = s;
    }
    if (gtid < T_STEPS) {
        float R  = expf(2.0f * lon[0]);
        float g0 = expf(2.0f * lbs[0]);
        float den0 = fmaf((float)gtid, g0, R);   // R + t*g0
        float den1 = den0 + g0;                  // R + (t+1)*g0
        g_itg[gtid] = g0 * frcp(den0);           // kap numerator for prefix form
        g_iaT[gtid] = den0 * frcp(den1) * frcp(R); // 1/alpha_t
    }
}

// ---------- K2: per-sensor chains via prefix sums (delta_t closed form) ----
__global__ void __launch_bounds__(64) sensor_kernel(const float* __restrict__ obs) {
    __shared__ float sh[64];
    const int s = blockIdx.x, j = threadIdx.x;
    const int comp = s >> 6;
    const float* yb = g_ybar + comp;
    const int t0 = j * WIN;
    float sum = 0.0f;
    #pragma unroll 8
    for (int i = 0; i < WIN; ++i) {
        int t = t0 + i;
        sum += obs[t * OBS + s] - yb[2 * t];
    }
    sh[j] = sum;
    __syncthreads();
    float S = 0.0f;
    for (int k = 0; k < j; ++k) S += sh[k];     // exclusive chunk prefix
    __syncthreads();
    float acc = 0.0f;
    #pragma unroll 8
    for (int i = 0; i < WIN; ++i) {
        int t = t0 + i;
        float x  = obs[t * OBS + s] - yb[2 * t];
        float rt = fmaf(-S, g_itg[t], x);       // x_t - g0*S_{t-1}/(R+t*g0)
        S += x;
        acc = fmaf(g_iaT[t], rt * rt, acc);
    }
    sh[j] = acc;
    __syncthreads();
    if (j == 0) {
        float a = 0.0f;
        for (int k = 0; k < 64; ++k) a += sh[k];
        g_acc[s] = a;
    }
}

// ---------- main kernel smem layout (float offsets) ----------
#define OFF_G    0            // float4[4096]
#define OFF_YB   16384        // float2[4096]
#define OFF_BND  24576        // (CH+1)*6 = 294 (reserve 300)
#define OFF_CMP  24876        // 48*12 = 576
#define OFF_LLQ  25452        // 48
#define OFF_LD   25500        // 256
#define OFF_FIT  25756        // 16
#define OFF_PUB  25772        // 16
#define OFF_ACC  25788        // 128
#define SMEM_FLOATS 25916
#define SMEM_BYTES  (SMEM_FLOATS * 4)

// Lagrange nodes x = 1/tau at tau = 512, 768, 1024
#define XA (1.0f / 512.0f)
#define XB (1.0f / 768.0f)
#define XC (1.0f / 1024.0f)
#define IDA ( 1572864.0f)
#define IDB (-4718592.0f)
#define IDC ( 3145728.0f)

__global__ void __launch_bounds__(256, 1) kalman_kernel(
    const float* __restrict__ lbs,
    const float* __restrict__ lon,
    const float* __restrict__ ltn,
    float* __restrict__ out)
{
    extern __shared__ float smem[];
    float4* Gp    = (float4*)(smem + OFF_G);
    float2* ybp   = (float2*)(smem + OFF_YB);
    float*  s_bnd = smem + OFF_BND;
    float*  s_cmp = smem + OFF_CMP;
    float*  s_llq = smem + OFF_LLQ;
    float*  s_ld  = smem + OFF_LD;
    float*  s_fit = smem + OFF_FIT;
    float*  s_pub = smem + OFF_PUB;
    float*  s_acc = smem + OFF_ACC;

    const int tid  = threadIdx.x;
    const int wid  = tid >> 5;
    const int lane = tid & 31;

    const float R  = expf(2.0f * lon[0]);
    const float q  = expf(2.0f * ltn[0]);
    const float g0 = expf(2.0f * lbs[0]);
    const float q1 = q, q2 = 0.5f * q, q3 = q * (1.0f / 3.0f);
    const float R64 = R * 0.015625f;

    {   // stage ybar + sensor accs
        const float4* src = (const float4*)g_ybar;
        float4*       dst = (float4*)ybp;
        #pragma unroll
        for (int i = tid; i < 2 * T_STEPS / 4; i += 256) dst[i] = src[i];
    }
    if (tid < OBS) s_acc[tid] = g_acc[tid];
    __syncthreads();

    // ================= phase 1: serial region t < 1024 =================
    if (wid == 0) {
        float a = 100.0f, c = 100.0f, d = 0.0f;
        float E = 0.0f, F = 0.0f, G = g0 * 0.015625f;
        float is = 1.0f;
        const bool st = (lane == 0);
        for (int w = 0; w < NW1; ++w) {
            const bool exact = (w == 0);
            #pragma unroll 8
            for (int j = 0; j < WIN; ++j) {
                float cp = c + q1;
                float dp = (d + c) + q2;
                float ap = fmaf(2.0f, d, a) + (c + q3);
                float Ep = E + F;
                float u1 = ap + Ep;
                float u2 = dp + F;
                float u3 = Ep + G;
                float Sv = (u1 + u3) + R64;
                if (exact) is = frcp(Sv);
                else       is = is * fmaf(-Sv, is, 2.0f);  // Newton
                float k1 = u1 * is, k2 = u2 * is, k3 = u3 * is;
                a = fmaf(-k1, u1, ap);
                d = fmaf(-k1, u2, dp);
                c = fmaf(-k2, u2, cp);
                E = fmaf(-k1, u3, Ep);
                F = fmaf(-k2, u3, F);
                G = fmaf(-k3, u3, G);
                if (st) Gp[w * WIN + j] = make_float4(k1, k2, k3, is);
            }
            if (st) {
                if (w == 7)  { s_fit[0] = a; s_fit[1] = d; s_fit[2] = c; }
                if (w == 11) { s_fit[3] = a; s_fit[4] = d; s_fit[5] = c; }
                if (w == 15) { s_fit[6] = a; s_fit[7] = d; s_fit[8] = c; }
            }
            asm volatile("bar.sync 1, 64;" ::: "memory");
        }
    } else if (wid == 1) {
        float m0 = 0.f, m1 = 0.f, V0 = 0.f, V1 = 0.f;
        float mV0 = 0.f, mV1 = 0.f, PV0 = 0.f, PV1 = 0.f;
        float llq = 0.f;
        for (int w = 0; w < NW1; ++w) {
            asm volatile("bar.sync 1, 64;" ::: "memory");
            const int tb = w * WIN;
            #pragma unroll 8
            for (int j = 0; j < WIN; ++j) {
                float4 g  = Gp[tb + j];
                float2 yb = ybp[tb + j];
                float k12 = g.x + g.y;
                float km  = k12 + g.z;
                float Ib0 = yb.x - m0;
                float Ib1 = yb.y - m1;
                float vu0 = fmaf(g.y, Ib0, V0);
                float vu1 = fmaf(g.y, Ib1, V1);
                float mn0 = fmaf(km, Ib0, mV0);
                float mn1 = fmaf(km, Ib1, mV1);
                float Pn0 = fmaf(k12, Ib0, PV0);
                float Pn1 = fmaf(k12, Ib1, PV1);
                mV0 = mn0 + vu0;  mV1 = mn1 + vu1;
                PV0 = Pn0 + vu0;  PV1 = Pn1 + vu1;
                m0 = mn0;  m1 = mn1;
                V0 = vu0;  V1 = vu1;
                float ss = fmaf(Ib1, Ib1, Ib0 * Ib0);
                llq = fmaf(g.w, ss, llq);
            }
        }
        if (lane == 0) {
            s_pub[0] = m0; s_pub[1] = V0; s_pub[2] = PV0;
            s_pub[3] = m1; s_pub[4] = V1; s_pub[5] = PV1;
            s_pub[6] = llq;
        }
    }
    __syncthreads();

    // ======= phase 2a: fitted gains for t >= 1024 + logdet partials =======
    {
        float4 fa = Gp[511], fb = Gp[767], fc = Gp[1023];
        float ls = 0.0f;
        for (int t = tid; t < T_STEPS; t += 256) {
            float4 g;
            if (t >= T1) {
                float x  = frcp((float)(t + 1));
                float ea = x - XA, eb = x - XB, ec = x - XC;
                float L0 = eb * ec * IDA;
                float L1 = ea * ec * IDB;
                float L2 = ea * eb * IDC;
                g.x = fmaf(L0, fa.x, fmaf(L1, fb.x, L2 * fc.x));
                g.y = fmaf(L0, fa.y, fmaf(L1, fb.y, L2 * fc.y));
                g.z = fmaf(L0, fa.z, fmaf(L1, fb.z, L2 * fc.z));
                g.w = fmaf(L0, fa.w, fmaf(L1, fb.w, L2 * fc.w));
                Gp[t] = g;
            } else {
                g = Gp[t];
            }
            ls += __log2f(g.w);
        }
        s_ld[tid] = ls;
    }
    __syncthreads();

    // ===== phase 2b: compose per-chunk affine maps (state s=(m,V,PV)) =====
    if (tid < CH) {
        float c11 = 1.f, c21 = 0.f, c31 = 0.f;   // column for m
        float c12 = 0.f, c22 = 1.f, c32 = 0.f;   // column for V
        float bx1 = 0.f, bx2 = 0.f, bx3 = 0.f;   // offset (x comp)
        float by1 = 0.f, by2 = 0.f, by3 = 0.f;   // offset (y comp)
        const int base = T1 + tid * WIN;
        #pragma unroll 4
        for (int j = 0; j < WIN; ++j) {
            float4 g  = Gp[base + j];
            float2 yb = ybp[base + j];
            float k2v = g.y;
            float k12 = g.x + g.y;
            float km  = k12 + g.z;
            float k31 = k12 + k2v;
            {   // m-column
                float n1 = fmaf(-km,  c11, c11 + c21);
                float n2 = fmaf(-k2v, c11, c21);
                float n3 = fmaf(-k31, c11, c21 + c31);
                c11 = n1; c21 = n2; c31 = n3;
            }
            {   // V-column
                float n1 = fmaf(-km,  c12, c12 + c22);
                float n2 = fmaf(-k2v, c12, c22);
                float n3 = fmaf(-k31, c12, c22 + c32);
                c12 = n1; c22 = n2; c32 = n3;
            }
            {   // offsets
                float n1 = fmaf(km,  yb.x, fmaf(-km,  bx1, bx1 + bx2));
                float n2 = fmaf(k2v, yb.x, fmaf(-k2v, bx1, bx2));
                float n3 = fmaf(k31, yb.x, fmaf(-k31, bx1, bx2 + bx3));
                bx1 = n1; bx2 = n2; bx3 = n3;
                float p1 = fmaf(km,  yb.y, fmaf(-km,  by1, by1 + by2));
                float p2 = fmaf(k2v, yb.y, fmaf(-k2v, by1, by2));
                float p3 = fmaf(k31, yb.y, fmaf(-k31, by1, by2 + by3));
                by1 = p1; by2 = p2; by3 = p3;
            }
        }
        float* r = s_cmp + tid * 12;
        r[0] = c11; r[1] = c21; r[2] = c31;
        r[3] = c12; r[4] = c22; r[5] = c32;
        r[6] = bx1; r[7] = bx2; r[8] = bx3;
        r[9] = by1; r[10] = by2; r[11] = by3;
    }
    __syncthreads();

    // ========== phase 2c: sequential combine across 48 chunks ==========
    if (tid == 0) {
        float m0 = s_pub[0], V0 = s_pub[1], PV0 = s_pub[2];
        float m1 = s_pub[3], V1 = s_pub[4], PV1 = s_pub[5];
        s_bnd[0] = m0; s_bnd[1] = V0; s_bnd[2] = PV0;
        s_bnd[3] = m1; s_bnd[4] = V1; s_bnd[5] = PV1;
        for (int k = 0; k < CH; ++k) {
            const float* r = s_cmp + k * 12;
            float n0  = fmaf(r[0], m0, fmaf(r[3], V0, r[6]));
            float nV0 = fmaf(r[1], m0, fmaf(r[4], V0, r[7]));
            float nP0 = fmaf(r[2], m0, fmaf(r[5], V0, PV0 + r[8]));
            float n1  = fmaf(r[0], m1, fmaf(r[3], V1, r[9]));
            float nV1 = fmaf(r[1], m1, fmaf(r[4], V1, r[10]));
            float nP1 = fmaf(r[2], m1, fmaf(r[5], V1, PV1 + r[11]));
            m0 = n0; V0 = nV0; PV0 = nP0;
            m1 = n1; V1 = nV1; PV1 = nP1;
            float* b = s_bnd + (k + 1) * 6;
            b[0] = m0; b[1] = V0; b[2] = PV0;
            b[3] = m1; b[4] = V1; b[5] = PV1;
        }
    }
    __syncthreads();

    // ========== phase 2d: replay chunks for llq + final state ==========
    if (tid < CH) {
        const float* b = s_bnd + tid * 6;
        float m0 = b[0], V0 = b[1], PV0 = b[2];
        float m1 = b[3], V1 = b[4], PV1 = b[5];
        float mV0 = m0 + V0, mV1 = m1 + V1;
        float Pn0 = 0.f, Pn1 = 0.f, llq = 0.f;
        const int base = T1 + tid * WIN;
        #pragma unroll 4
        for (int j = 0; j < WIN; ++j) {
            float4 g  = Gp[base + j];
            float2 yb = ybp[base + j];
            float k12 = g.x + g.y;
            float km  = k12 + g.z;
            float Ib0 = yb.x - m0;
            float Ib1 = yb.y - m1;
            float vu0 = fmaf(g.y, Ib0, V0);
            float vu1 = fmaf(g.y, Ib1, V1);
            float mn0 = fmaf(km, Ib0, mV0);
            float mn1 = fmaf(km, Ib1, mV1);
            Pn0 = fmaf(k12, Ib0, PV0);
            Pn1 = fmaf(k12, Ib1, PV1);
            mV0 = mn0 + vu0;  mV1 = mn1 + vu1;
            PV0 = Pn0 + vu0;  PV1 = Pn1 + vu1;
            m0 = mn0;  m1 = mn1;
            V0 = vu0;  V1 = vu1;
            float ss = fmaf(Ib1, Ib1, Ib0 * Ib0);
            llq = fmaf(g.w, ss, llq);
        }
        s_llq[tid] = llq;
        if (tid == CH - 1) {
            s_pub[8]  = Pn0 - V0;  s_pub[9]  = Pn1 - V1;   // posterior pos
            s_pub[10] = V0;        s_pub[11] = V1;          // posterior vel
        }
    }
    __syncthreads();

    if (tid == 0) {
        float atot = 0.0f;
        #pragma unroll 8
        for (int i = 0; i < OBS; ++i) atot += s_acc[i];
        float lsum = 0.0f;
        #pragma unroll 8
        for (int i = 0; i < 256; ++i) lsum += s_ld[i];
        float llq = s_pub[6];
        for (int i = 0; i < CH; ++i) llq += s_llq[i];
        // covariance at T via Lagrange extrapolation to x = 1/4096
        float x  = 1.0f / 4096.0f;
        float ea = x - XA, eb = x - XB, ec = x - XC;
        float L0 = eb * ec * IDA;
        float L1 = ea * ec * IDB;
        float L2 = ea * eb * IDC;
        float a = fmaf(L0, s_fit[0], fmaf(L1, s_fit[3], L2 * s_fit[6]));
        float d = fmaf(L0, s_fit[1], fmaf(L1, s_fit[4], L2 * s_fit[7]));
        float c = fmaf(L0, s_fit[2], fmaf(L1, s_fit[5], L2 * s_fit[8]));

        double ldS = -(double)lsum;                     // sum log2(Sv)
        double ldA = (double)(T_STEPS - 1) * log2((double)R)
                   + log2((double)R + (double)T_STEPS * (double)g0);
        double ld  = 63.0 * ldA + ldS + 6.0 * (double)T_STEPS;
        const double LN2    = 0.6931471805599453094;
        const double LOG2PI = 1.8378770664093454836;
        double quad = 0.5 * ((double)atot + (double)llq);
        double logp = -quad - ld * LN2 - 64.0 * (double)T_STEPS * LOG2PI;
        out[0] = (float)logp;
        out[1] = s_pub[8];  out[2] = s_pub[9];
        out[3] = s_pub[10]; out[4] = s_pub[11];
        out[5]  = a;   out[6]  = 0.f; out[7]  = d;   out[8]  = 0.f;
        out[9]  = 0.f; out[10] = a;   out[11] = 0.f; out[12] = d;
        out[13] = d;   out[14] = 0.f; out[15] = c;   out[16] = 0.f;
        out[17] = 0.f; out[18] = d;   out[19] = 0.f; out[20] = c;
    }
}

extern "C" void kernel_launch(void* const* d_in, const int* in_sizes, int n_in,
                              void* d_out, int out_size) {
    const float* obs = (const float*)d_in[0];
    const float* lbs = (const float*)d_in[1];
    const float* lon = (const float*)d_in[2];
    const float* ltn = (const float*)d_in[3];
    float* out = (float*)d_out;
    (void)in_sizes; (void)n_in; (void)out_size;

    static bool attr_set = false;
    if (!attr_set) {
        cudaFuncSetAttribute(kalman_kernel,
                             cudaFuncAttributeMaxDynamicSharedMemorySize,
                             SMEM_BYTES);
        attr_set = true;
    }
    prep_kernel<<<64, 256>>>((const float4*)obs, lbs, lon);
    sensor_kernel<<<OBS, 64>>>(obs);
    kalman_kernel<<<1, 256, SMEM_BYTES>>>(lbs, lon, ltn, out);
}

// round 8
// speedup vs baseline: 2.5797x; 1.3469x over previous
#include <cuda_runtime.h>

// Kalman: NCV(4) + 128 static sensor biases, T=4096.
// Round 8: shrink the serial region to t<256 (nodes tau=128/192/256) and
// widen the prep grid. Scheme validated round 7 at T1=1024:
//  - Serial Riccati (warp0) + serial mean chain (warp1) for t<T1, pipelined
//    via named barrier 1.
//  - Gains for t>=T1 via quadratic Lagrange extrapolation in x=1/tau.
//  - Mean chain t>=T1 via blocked affine scan (60 chunks x 64 steps).
//  - Sensor bias chains are a scaled prefix sum -> parallel prepass kernel.

#define T_STEPS 4096
#define OBS 128
#define T1 256
#define WIN 64
#define NW1 (T1 / WIN)
#define CH ((T_STEPS - T1) / WIN)

__device__ float g_ybar[2 * T_STEPS];
__device__ float g_itg[T_STEPS];
__device__ float g_iaT[T_STEPS];
__device__ float g_acc[OBS];

__device__ __forceinline__ float frcp(float x) {
    float r;
    asm("rcp.approx.f32 %0, %1;" : "=f"(r) : "f"(x));
    return r;
}

// ---------- K1: per-step obs group means + scalar tables ----------
__global__ void prep_kernel(const float4* __restrict__ obs4,
                            const float* __restrict__ lbs,
                            const float* __restrict__ lon) {
    int gtid = blockIdx.x * blockDim.x + threadIdx.x;
    int gw = gtid >> 5, lane = gtid & 31;
    int nw = (gridDim.x * blockDim.x) >> 5;
    for (int t = gw; t < T_STEPS; t += nw) {
        float4 v = obs4[t * 32 + lane];
        // lanes 0..15: obs 0..63 (x group); lanes 16..31: obs 64..127 (y)
        float s = (v.x + v.y) + (v.z + v.w);
        #pragma unroll
        for (int m = 8; m; m >>= 1)
            s += __shfl_xor_sync(0xffffffffu, s, m);
        s *= 0.015625f;
        if (lane == 0)  g_ybar[2 * t]     = s;
        if (lane == 16) g_ybar[2 * t + 1] = s;
    }
    if (gtid < T_STEPS) {
        float R  = expf(2.0f * lon[0]);
        float g0 = expf(2.0f * lbs[0]);
        float den0 = fmaf((float)gtid, g0, R);     // R + t*g0
        float den1 = den0 + g0;                    // R + (t+1)*g0
        g_itg[gtid] = g0 * frcp(den0);
        g_iaT[gtid] = den0 * frcp(den1) * frcp(R); // 1/alpha_t
    }
}

// ---------- K2: per-sensor chains via prefix sums (delta_t closed form) ----
__global__ void __launch_bounds__(64) sensor_kernel(const float* __restrict__ obs) {
    __shared__ float sh[64];
    const int s = blockIdx.x, j = threadIdx.x;
    const int comp = s >> 6;
    const float* yb = g_ybar + comp;
    const int t0 = j * WIN;
    float sum = 0.0f;
    #pragma unroll 8
    for (int i = 0; i < WIN; ++i) {
        int t = t0 + i;
        sum += obs[t * OBS + s] - yb[2 * t];
    }
    sh[j] = sum;
    __syncthreads();
    float S = 0.0f;
    for (int k = 0; k < j; ++k) S += sh[k];     // exclusive chunk prefix
    __syncthreads();
    float acc = 0.0f;
    #pragma unroll 8
    for (int i = 0; i < WIN; ++i) {
        int t = t0 + i;
        float x  = obs[t * OBS + s] - yb[2 * t];
        float rt = fmaf(-S, g_itg[t], x);       // x_t - g0*S_{t-1}/(R+t*g0)
        S += x;
        acc = fmaf(g_iaT[t], rt * rt, acc);
    }
    sh[j] = acc;
    __syncthreads();
    if (j == 0) {
        float a = 0.0f;
        for (int k = 0; k < 64; ++k) a += sh[k];
        g_acc[s] = a;
    }
}

// ---------- main kernel smem layout (float offsets) ----------
#define OFF_G    0            // float4[4096]  -> 16384
#define OFF_YB   16384        // float2[4096]  ->  8192
#define OFF_BND  24576        // (CH+1)*6 = 366 (reserve 368)
#define OFF_CMP  24944        // CH*12 = 720
#define OFF_LLQ  25664        // 64
#define OFF_LD   25728        // 256
#define OFF_FIT  25984        // 16
#define OFF_PUB  26000        // 16
#define OFF_ACC  26016        // 128
#define SMEM_FLOATS 26144
#define SMEM_BYTES  (SMEM_FLOATS * 4)

// Lagrange nodes x = 1/tau at tau = 128, 192, 256
#define XA (1.0f / 128.0f)
#define XB (1.0f / 192.0f)
#define XC (1.0f / 256.0f)
#define IDA (  98304.0f)
#define IDB (-294912.0f)
#define IDC ( 196608.0f)

__global__ void __launch_bounds__(256, 1) kalman_kernel(
    const float* __restrict__ lbs,
    const float* __restrict__ lon,
    const float* __restrict__ ltn,
    float* __restrict__ out)
{
    extern __shared__ float smem[];
    float4* Gp    = (float4*)(smem + OFF_G);
    float2* ybp   = (float2*)(smem + OFF_YB);
    float*  s_bnd = smem + OFF_BND;
    float*  s_cmp = smem + OFF_CMP;
    float*  s_llq = smem + OFF_LLQ;
    float*  s_ld  = smem + OFF_LD;
    float*  s_fit = smem + OFF_FIT;
    float*  s_pub = smem + OFF_PUB;
    float*  s_acc = smem + OFF_ACC;

    const int tid  = threadIdx.x;
    const int wid  = tid >> 5;
    const int lane = tid & 31;

    const float R  = expf(2.0f * lon[0]);
    const float q  = expf(2.0f * ltn[0]);
    const float g0 = expf(2.0f * lbs[0]);
    const float q1 = q, q2 = 0.5f * q, q3 = q * (1.0f / 3.0f);
    const float R64 = R * 0.015625f;

    {   // stage ybar + sensor accs
        const float4* src = (const float4*)g_ybar;
        float4*       dst = (float4*)ybp;
        #pragma unroll
        for (int i = tid; i < 2 * T_STEPS / 4; i += 256) dst[i] = src[i];
    }
    if (tid < OBS) s_acc[tid] = g_acc[tid];
    __syncthreads();

    // ================= phase 1: serial region t < T1 =================
    if (wid == 0) {
        float a = 100.0f, c = 100.0f, d = 0.0f;
        float E = 0.0f, F = 0.0f, G = g0 * 0.015625f;
        float is = 1.0f;
        const bool st = (lane == 0);
        for (int w = 0; w < NW1; ++w) {
            const bool exact = (w == 0);
            #pragma unroll 8
            for (int j = 0; j < WIN; ++j) {
                float cp = c + q1;
                float dp = (d + c) + q2;
                float ap = fmaf(2.0f, d, a) + (c + q3);
                float Ep = E + F;
                float u1 = ap + Ep;
                float u2 = dp + F;
                float u3 = Ep + G;
                float Sv = (u1 + u3) + R64;
                if (exact) is = frcp(Sv);
                else       is = is * fmaf(-Sv, is, 2.0f);  // Newton
                float k1 = u1 * is, k2 = u2 * is, k3 = u3 * is;
                a = fmaf(-k1, u1, ap);
                d = fmaf(-k1, u2, dp);
                c = fmaf(-k2, u2, cp);
                E = fmaf(-k1, u3, Ep);
                F = fmaf(-k2, u3, F);
                G = fmaf(-k3, u3, G);
                if (st) Gp[w * WIN + j] = make_float4(k1, k2, k3, is);
            }
            if (st) {
                if (w == 1) { s_fit[0] = a; s_fit[1] = d; s_fit[2] = c; }
                if (w == 2) { s_fit[3] = a; s_fit[4] = d; s_fit[5] = c; }
                if (w == 3) { s_fit[6] = a; s_fit[7] = d; s_fit[8] = c; }
            }
            asm volatile("bar.sync 1, 64;" ::: "memory");
        }
    } else if (wid == 1) {
        float m0 = 0.f, m1 = 0.f, V0 = 0.f, V1 = 0.f;
        float mV0 = 0.f, mV1 = 0.f, PV0 = 0.f, PV1 = 0.f;
        float llq = 0.f;
        for (int w = 0; w < NW1; ++w) {
            asm volatile("bar.sync 1, 64;" ::: "memory");
            const int tb = w * WIN;
            #pragma unroll 8
            for (int j = 0; j < WIN; ++j) {
                float4 g  = Gp[tb + j];
                float2 yb = ybp[tb + j];
                float k12 = g.x + g.y;
                float km  = k12 + g.z;
                float Ib0 = yb.x - m0;
                float Ib1 = yb.y - m1;
                float vu0 = fmaf(g.y, Ib0, V0);
                float vu1 = fmaf(g.y, Ib1, V1);
                float mn0 = fmaf(km, Ib0, mV0);
                float mn1 = fmaf(km, Ib1, mV1);
                float Pn0 = fmaf(k12, Ib0, PV0);
                float Pn1 = fmaf(k12, Ib1, PV1);
                mV0 = mn0 + vu0;  mV1 = mn1 + vu1;
                PV0 = Pn0 + vu0;  PV1 = Pn1 + vu1;
                m0 = mn0;  m1 = mn1;
                V0 = vu0;  V1 = vu1;
                float ss = fmaf(Ib1, Ib1, Ib0 * Ib0);
                llq = fmaf(g.w, ss, llq);
            }
        }
        if (lane == 0) {
            s_pub[0] = m0; s_pub[1] = V0; s_pub[2] = PV0;
            s_pub[3] = m1; s_pub[4] = V1; s_pub[5] = PV1;
            s_pub[6] = llq;
        }
    }
    __syncthreads();

    // ======= phase 2a: fitted gains for t >= T1 + logdet partials =======
    {
        float4 fa = Gp[127], fb = Gp[191], fc = Gp[255];
        float ls = 0.0f;
        for (int t = tid; t < T_STEPS; t += 256) {
            float4 g;
            if (t >= T1) {
                float x  = frcp((float)(t + 1));
                float ea = x - XA, eb = x - XB, ec = x - XC;
                float L0 = eb * ec * IDA;
                float L1 = ea * ec * IDB;
                float L2 = ea * eb * IDC;
                g.x = fmaf(L0, fa.x, fmaf(L1, fb.x, L2 * fc.x));
                g.y = fmaf(L0, fa.y, fmaf(L1, fb.y, L2 * fc.y));
                g.z = fmaf(L0, fa.z, fmaf(L1, fb.z, L2 * fc.z));
                g.w = fmaf(L0, fa.w, fmaf(L1, fb.w, L2 * fc.w));
                Gp[t] = g;
            } else {
                g = Gp[t];
            }
            ls += __log2f(g.w);
        }
        s_ld[tid] = ls;
    }
    __syncthreads();

    // ===== phase 2b: compose per-chunk affine maps (state s=(m,V,PV)) =====
    if (tid < CH) {
        float c11 = 1.f, c21 = 0.f, c31 = 0.f;   // column for m
        float c12 = 0.f, c22 = 1.f, c32 = 0.f;   // column for V
        float bx1 = 0.f, bx2 = 0.f, bx3 = 0.f;   // offset (x comp)
        float by1 = 0.f, by2 = 0.f, by3 = 0.f;   // offset (y comp)
        const int base = T1 + tid * WIN;
        #pragma unroll 4
        for (int j = 0; j < WIN; ++j) {
            float4 g  = Gp[base + j];
            float2 yb = ybp[base + j];
            float k2v = g.y;
            float k12 = g.x + g.y;
            float km  = k12 + g.z;
            float k31 = k12 + k2v;
            {   // m-column
                float n1 = fmaf(-km,  c11, c11 + c21);
                float n2 = fmaf(-k2v, c11, c21);
                float n3 = fmaf(-k31, c11, c21 + c31);
                c11 = n1; c21 = n2; c31 = n3;
            }
            {   // V-column
                float n1 = fmaf(-km,  c12, c12 + c22);
                float n2 = fmaf(-k2v, c12, c22);
                float n3 = fmaf(-k31, c12, c22 + c32);
                c12 = n1; c22 = n2; c32 = n3;
            }
            {   // offsets
                float n1 = fmaf(km,  yb.x, fmaf(-km,  bx1, bx1 + bx2));
                float n2 = fmaf(k2v, yb.x, fmaf(-k2v, bx1, bx2));
                float n3 = fmaf(k31, yb.x, fmaf(-k31, bx1, bx2 + bx3));
                bx1 = n1; bx2 = n2; bx3 = n3;
                float p1 = fmaf(km,  yb.y, fmaf(-km,  by1, by1 + by2));
                float p2 = fmaf(k2v, yb.y, fmaf(-k2v, by1, by2));
                float p3 = fmaf(k31, yb.y, fmaf(-k31, by1, by2 + by3));
                by1 = p1; by2 = p2; by3 = p3;
            }
        }
        float* r = s_cmp + tid * 12;
        r[0] = c11; r[1] = c21; r[2] = c31;
        r[3] = c12; r[4] = c22; r[5] = c32;
        r[6] = bx1; r[7] = bx2; r[8] = bx3;
        r[9] = by1; r[10] = by2; r[11] = by3;
    }
    __syncthreads();

    // ========== phase 2c: sequential combine across CH chunks ==========
    if (tid == 0) {
        float m0 = s_pub[0], V0 = s_pub[1], PV0 = s_pub[2];
        float m1 = s_pub[3], V1 = s_pub[4], PV1 = s_pub[5];
        s_bnd[0] = m0; s_bnd[1] = V0; s_bnd[2] = PV0;
        s_bnd[3] = m1; s_bnd[4] = V1; s_bnd[5] = PV1;
        for (int k = 0; k < CH; ++k) {
            const float* r = s_cmp + k * 12;
            float n0  = fmaf(r[0], m0, fmaf(r[3], V0, r[6]));
            float nV0 = fmaf(r[1], m0, fmaf(r[4], V0, r[7]));
            float nP0 = fmaf(r[2], m0, fmaf(r[5], V0, PV0 + r[8]));
            float n1  = fmaf(r[0], m1, fmaf(r[3], V1, r[9]));
            float nV1 = fmaf(r[1], m1, fmaf(r[4], V1, r[10]));
            float nP1 = fmaf(r[2], m1, fmaf(r[5], V1, PV1 + r[11]));
            m0 = n0; V0 = nV0; PV0 = nP0;
            m1 = n1; V1 = nV1; PV1 = nP1;
            float* b = s_bnd + (k + 1) * 6;
            b[0] = m0; b[1] = V0; b[2] = PV0;
            b[3] = m1; b[4] = V1; b[5] = PV1;
        }
    }
    __syncthreads();

    // ========== phase 2d: replay chunks for llq + final state ==========
    if (tid < CH) {
        const float* b = s_bnd + tid * 6;
        float m0 = b[0], V0 = b[1], PV0 = b[2];
        float m1 = b[3], V1 = b[4], PV1 = b[5];
        float mV0 = m0 + V0, mV1 = m1 + V1;
        float Pn0 = 0.f, Pn1 = 0.f, llq = 0.f;
        const int base = T1 + tid * WIN;
        #pragma unroll 4
        for (int j = 0; j < WIN; ++j) {
            float4 g  = Gp[base + j];
            float2 yb = ybp[base + j];
            float k12 = g.x + g.y;
            float km  = k12 + g.z;
            float Ib0 = yb.x - m0;
            float Ib1 = yb.y - m1;
            float vu0 = fmaf(g.y, Ib0, V0);
            float vu1 = fmaf(g.y, Ib1, V1);
            float mn0 = fmaf(km, Ib0, mV0);
            float mn1 = fmaf(km, Ib1, mV1);
            Pn0 = fmaf(k12, Ib0, PV0);
            Pn1 = fmaf(k12, Ib1, PV1);
            mV0 = mn0 + vu0;  mV1 = mn1 + vu1;
            PV0 = Pn0 + vu0;  PV1 = Pn1 + vu1;
            m0 = mn0;  m1 = mn1;
            V0 = vu0;  V1 = vu1;
            float ss = fmaf(Ib1, Ib1, Ib0 * Ib0);
            llq = fmaf(g.w, ss, llq);
        }
        s_llq[tid] = llq;
        if (tid == CH - 1) {
            s_pub[8]  = Pn0 - V0;  s_pub[9]  = Pn1 - V1;   // posterior pos
            s_pub[10] = V0;        s_pub[11] = V1;          // posterior vel
        }
    }
    __syncthreads();

    if (tid == 0) {
        float atot = 0.0f;
        #pragma unroll 8
        for (int i = 0; i < OBS; ++i) atot += s_acc[i];
        float lsum = 0.0f;
        #pragma unroll 8
        for (int i = 0; i < 256; ++i) lsum += s_ld[i];
        float llq = s_pub[6];
        for (int i = 0; i < CH; ++i) llq += s_llq[i];
        // covariance at T via Lagrange extrapolation to x = 1/4096
        float x  = 1.0f / 4096.0f;
        float ea = x - XA, eb = x - XB, ec = x - XC;
        float L0 = eb * ec * IDA;
        float L1 = ea * ec * IDB;
        float L2 = ea * eb * IDC;
        float a = fmaf(L0, s_fit[0], fmaf(L1, s_fit[3], L2 * s_fit[6]));
        float d = fmaf(L0, s_fit[1], fmaf(L1, s_fit[4], L2 * s_fit[7]));
        float c = fmaf(L0, s_fit[2], fmaf(L1, s_fit[5], L2 * s_fit[8]));

        double ldS = -(double)lsum;                     // sum log2(Sv)
        double ldA = (double)(T_STEPS - 1) * log2((double)R)
                   + log2((double)R + (double)T_STEPS * (double)g0);
        double ld  = 63.0 * ldA + ldS + 6.0 * (double)T_STEPS;
        const double LN2    = 0.6931471805599453094;
        const double LOG2PI = 1.8378770664093454836;
        double quad = 0.5 * ((double)atot + (double)llq);
        double logp = -quad - ld * LN2 - 64.0 * (double)T_STEPS * LOG2PI;
        out[0] = (float)logp;
        out[1] = s_pub[8];  out[2] = s_pub[9];
        out[3] = s_pub[10]; out[4] = s_pub[11];
        out[5]  = a;   out[6]  = 0.f; out[7]  = d;   out[8]  = 0.f;
        out[9]  = 0.f; out[10] = a;   out[11] = 0.f; out[12] = d;
        out[13] = d;   out[14] = 0.f; out[15] = c;   out[16] = 0.f;
        out[17] = 0.f; out[18] = d;   out[19] = 0.f; out[20] = c;
    }
}

extern "C" void kernel_launch(void* const* d_in, const int* in_sizes, int n_in,
                              void* d_out, int out_size) {
    const float* obs = (const float*)d_in[0];
    const float* lbs = (const float*)d_in[1];
    const float* lon = (const float*)d_in[2];
    const float* ltn = (const float*)d_in[3];
    float* out = (float*)d_out;
    (void)in_sizes; (void)n_in; (void)out_size;

    static bool attr_set = false;
    if (!attr_set) {
        cudaFuncSetAttribute(kalman_kernel,
                             cudaFuncAttributeMaxDynamicSharedMemorySize,
                             SMEM_BYTES);
        attr_set = true;
    }
    prep_kernel<<<148, 256>>>((const float4*)obs, lbs, lon);
    sensor_kernel<<<OBS, 64>>>(obs);
    kalman_kernel<<<1, 256, SMEM_BYTES>>>(lbs, lon, ltn, out);
}

// round 9
// speedup vs baseline: 3.6806x; 1.4267x over previous
#include <cuda_runtime.h>

// Kalman: NCV(4) + 128 static sensor biases, T=4096.
// Round 9: single fused persistent kernel (65 blocks, all co-resident).
//   Workers 0..63 (one 64-step chunk each): obs tile -> ybar (ctrA),
//     sensor chunk sums (ctrB), prefix+replay quad-form partials (ctrC).
//   Master block 64: waits ctrA; serial Riccati+mean t<256 (warp0/warp1,
//     named barrier); Lagrange gain fill in 1/tau; 120x32 affine scan for
//     the mean chain; waits ctrC; final reduction; resets counters.
// All reductions fixed-order (deterministic); no device allocs; one launch.

#define T_STEPS 4096
#define OBS 128
#define T1 256
#define WIN 64
#define NW1 (T1 / WIN)
#define WIN2 32
#define CH2 ((T_STEPS - T1) / WIN2)   // 120
#define NCHK 64                        // worker chunks (64 steps each)

__device__ float g_ybar[2 * T_STEPS];
__device__ float g_csum[NCHK * OBS];
__device__ float g_accp[NCHK * OBS];
__device__ int   g_ctrA, g_ctrB, g_ctrC;

__device__ __forceinline__ float frcp(float x) {
    float r;
    asm("rcp.approx.f32 %0, %1;" : "=f"(r) : "f"(x));
    return r;
}

// ---- master smem layout (float offsets) ----
#define OFF_G    0            // float4[4096]  -> 16384
#define OFF_YB   16384        // float2[4096]  ->  8192
#define OFF_BND  24576        // (CH2+1)*6 = 726 -> 728
#define OFF_CMP  25304        // CH2*12 = 1440
#define OFF_LLQ  26744        // 128
#define OFF_LD   26872        // 256
#define OFF_FIT  27128        // 16
#define OFF_PUB  27144        // 16
#define OFF_ACC  27160        // 128
#define SMEM_FLOATS 27288
#define SMEM_BYTES  (SMEM_FLOATS * 4)

// Lagrange nodes x = 1/tau at tau = 128, 192, 256
#define XA (1.0f / 128.0f)
#define XB (1.0f / 192.0f)
#define XC (1.0f / 256.0f)
#define IDA (  98304.0f)
#define IDB (-294912.0f)
#define IDC ( 196608.0f)

__global__ void __launch_bounds__(256, 1) fused_kernel(
    const float4* __restrict__ obs4,
    const float* __restrict__ lbs,
    const float* __restrict__ lon,
    const float* __restrict__ ltn,
    float* __restrict__ out)
{
    extern __shared__ float smem[];
    const int tid  = threadIdx.x;
    const int bid  = blockIdx.x;

    const float R  = expf(2.0f * lon[0]);
    const float q  = expf(2.0f * ltn[0]);
    const float g0 = expf(2.0f * lbs[0]);

    if (bid < NCHK) {
        // ==================== WORKER block: chunk bid ====================
        float* tile = smem;            // [64][128] floats (32 KB)
        float* yloc = smem + 8192;     // [2*64]
        float* itg  = smem + 8320;     // [64]
        float* iaT  = smem + 8384;     // [64]
        const int c  = bid;
        const int c0 = c * WIN;
        const int w = tid >> 5, lane = tid & 31;

        // step 1: load tile + ybar for this chunk
        #pragma unroll
        for (int k = 0; k < 8; ++k) {
            int tl = w * 8 + k;
            int t  = c0 + tl;
            float4 v = obs4[t * 32 + lane];
            ((float4*)tile)[tl * 32 + lane] = v;
            float s = (v.x + v.y) + (v.z + v.w);
            #pragma unroll
            for (int m = 8; m; m >>= 1)
                s += __shfl_xor_sync(0xffffffffu, s, m);
            s *= 0.015625f;
            if (lane == 0)  { yloc[2 * tl]     = s; g_ybar[2 * t]     = s; }
            if (lane == 16) { yloc[2 * tl + 1] = s; g_ybar[2 * t + 1] = s; }
        }
        if (tid < WIN) {
            int t = c0 + tid;
            float den0 = fmaf((float)t, g0, R);
            float den1 = den0 + g0;
            itg[tid] = g0 * frcp(den0);
            iaT[tid] = den0 * frcp(den1) * frcp(R);
        }
        __syncthreads();
        if (tid == 0) { __threadfence(); atomicAdd(&g_ctrA, 1); }

        // step 2: per-sensor chunk sums
        if (tid < OBS) {
            const int comp = tid >> 6;
            float cs = 0.0f;
            #pragma unroll 8
            for (int i = 0; i < WIN; ++i)
                cs += tile[i * OBS + tid] - yloc[2 * i + comp];
            g_csum[c * OBS + tid] = cs;
        }
        __syncthreads();
        if (tid == 0) {
            __threadfence();
            atomicAdd(&g_ctrB, 1);
            while (*(volatile int*)&g_ctrB < NCHK) {}
        }
        __syncthreads();
        __threadfence();

        // step 3: exclusive prefix + replay quad-form partial
        if (tid < OBS) {
            float S = 0.0f;
            #pragma unroll 8
            for (int k = 0; k < c; ++k)
                S += g_csum[k * OBS + tid];
            const int comp = tid >> 6;
            float acc = 0.0f;
            #pragma unroll 8
            for (int i = 0; i < WIN; ++i) {
                float x  = tile[i * OBS + tid] - yloc[2 * i + comp];
                float rt = fmaf(-S, itg[i], x);
                S += x;
                acc = fmaf(iaT[i], rt * rt, acc);
            }
            g_accp[c * OBS + tid] = acc;
        }
        __syncthreads();
        if (tid == 0) { __threadfence(); atomicAdd(&g_ctrC, 1); }
        return;
    }

    // ======================= MASTER block =======================
    float4* Gp    = (float4*)(smem + OFF_G);
    float2* ybp   = (float2*)(smem + OFF_YB);
    float*  s_bnd = smem + OFF_BND;
    float*  s_cmp = smem + OFF_CMP;
    float*  s_llq = smem + OFF_LLQ;
    float*  s_ld  = smem + OFF_LD;
    float*  s_fit = smem + OFF_FIT;
    float*  s_pub = smem + OFF_PUB;
    float*  s_acc = smem + OFF_ACC;

    const int wid  = tid >> 5;
    const int lane = tid & 31;
    const float q1 = q, q2 = 0.5f * q, q3 = q * (1.0f / 3.0f);
    const float R64 = R * 0.015625f;

    if (tid == 0) { while (*(volatile int*)&g_ctrA < NCHK) {} }
    __syncthreads();
    __threadfence();

    {   // stage ybar
        const float4* src = (const float4*)g_ybar;
        float4*       dst = (float4*)ybp;
        #pragma unroll
        for (int i = tid; i < 2 * T_STEPS / 4; i += 256) dst[i] = src[i];
    }
    __syncthreads();

    // ---------------- phase 1: serial region t < T1 ----------------
    if (wid == 0) {
        float a = 100.0f, c = 100.0f, d = 0.0f;
        float E = 0.0f, F = 0.0f, G = g0 * 0.015625f;
        float is = 1.0f;
        const bool st = (lane == 0);
        for (int w = 0; w < NW1; ++w) {
            const bool exact = (w == 0);
            #pragma unroll 8
            for (int j = 0; j < WIN; ++j) {
                float cp = c + q1;
                float dp = (d + c) + q2;
                float ap = fmaf(2.0f, d, a) + (c + q3);
                float Ep = E + F;
                float u1 = ap + Ep;
                float u2 = dp + F;
                float u3 = Ep + G;
                float Sv = (u1 + u3) + R64;
                if (exact) is = frcp(Sv);
                else       is = is * fmaf(-Sv, is, 2.0f);
                float k1 = u1 * is, k2 = u2 * is, k3 = u3 * is;
                a = fmaf(-k1, u1, ap);
                d = fmaf(-k1, u2, dp);
                c = fmaf(-k2, u2, cp);
                E = fmaf(-k1, u3, Ep);
                F = fmaf(-k2, u3, F);
                G = fmaf(-k3, u3, G);
                if (st) Gp[w * WIN + j] = make_float4(k1, k2, k3, is);
            }
            if (st) {
                if (w == 1) { s_fit[0] = a; s_fit[1] = d; s_fit[2] = c; }
                if (w == 2) { s_fit[3] = a; s_fit[4] = d; s_fit[5] = c; }
                if (w == 3) { s_fit[6] = a; s_fit[7] = d; s_fit[8] = c; }
            }
            asm volatile("bar.sync 1, 64;" ::: "memory");
        }
    } else if (wid == 1) {
        float m0 = 0.f, m1 = 0.f, V0 = 0.f, V1 = 0.f;
        float mV0 = 0.f, mV1 = 0.f, PV0 = 0.f, PV1 = 0.f;
        float llq = 0.f;
        for (int w = 0; w < NW1; ++w) {
            asm volatile("bar.sync 1, 64;" ::: "memory");
            const int tb = w * WIN;
            #pragma unroll 8
            for (int j = 0; j < WIN; ++j) {
                float4 g  = Gp[tb + j];
                float2 yb = ybp[tb + j];
                float k12 = g.x + g.y;
                float km  = k12 + g.z;
                float Ib0 = yb.x - m0;
                float Ib1 = yb.y - m1;
                float vu0 = fmaf(g.y, Ib0, V0);
                float vu1 = fmaf(g.y, Ib1, V1);
                float mn0 = fmaf(km, Ib0, mV0);
                float mn1 = fmaf(km, Ib1, mV1);
                float Pn0 = fmaf(k12, Ib0, PV0);
                float Pn1 = fmaf(k12, Ib1, PV1);
                mV0 = mn0 + vu0;  mV1 = mn1 + vu1;
                PV0 = Pn0 + vu0;  PV1 = Pn1 + vu1;
                m0 = mn0;  m1 = mn1;
                V0 = vu0;  V1 = vu1;
                float ss = fmaf(Ib1, Ib1, Ib0 * Ib0);
                llq = fmaf(g.w, ss, llq);
            }
        }
        if (lane == 0) {
            s_pub[0] = m0; s_pub[1] = V0; s_pub[2] = PV0;
            s_pub[3] = m1; s_pub[4] = V1; s_pub[5] = PV1;
            s_pub[6] = llq;
        }
    }
    __syncthreads();

    // ------- phase 2a: fitted gains for t >= T1 + logdet partials -------
    {
        float4 fa = Gp[127], fb = Gp[191], fc = Gp[255];
        float ls = 0.0f;
        for (int t = tid; t < T_STEPS; t += 256) {
            float4 g;
            if (t >= T1) {
                float x  = frcp((float)(t + 1));
                float ea = x - XA, eb = x - XB, ec = x - XC;
                float L0 = eb * ec * IDA;
                float L1 = ea * ec * IDB;
                float L2 = ea * eb * IDC;
                g.x = fmaf(L0, fa.x, fmaf(L1, fb.x, L2 * fc.x));
                g.y = fmaf(L0, fa.y, fmaf(L1, fb.y, L2 * fc.y));
                g.z = fmaf(L0, fa.z, fmaf(L1, fb.z, L2 * fc.z));
                g.w = fmaf(L0, fa.w, fmaf(L1, fb.w, L2 * fc.w));
                Gp[t] = g;
            } else {
                g = Gp[t];
            }
            ls += __log2f(g.w);
        }
        s_ld[tid] = ls;
    }
    __syncthreads();

    // ---- phase 2b: compose per-chunk affine maps (s = (m, V, PV)) ----
    if (tid < CH2) {
        float c11 = 1.f, c21 = 0.f, c31 = 0.f;
        float c12 = 0.f, c22 = 1.f, c32 = 0.f;
        float bx1 = 0.f, bx2 = 0.f, bx3 = 0.f;
        float by1 = 0.f, by2 = 0.f, by3 = 0.f;
        const int base = T1 + tid * WIN2;
        #pragma unroll 4
        for (int j = 0; j < WIN2; ++j) {
            float4 g  = Gp[base + j];
            float2 yb = ybp[base + j];
            float k2v = g.y;
            float k12 = g.x + g.y;
            float km  = k12 + g.z;
            float k31 = k12 + k2v;
            {
                float n1 = fmaf(-km,  c11, c11 + c21);
                float n2 = fmaf(-k2v, c11, c21);
                float n3 = fmaf(-k31, c11, c21 + c31);
                c11 = n1; c21 = n2; c31 = n3;
            }
            {
                float n1 = fmaf(-km,  c12, c12 + c22);
                float n2 = fmaf(-k2v, c12, c22);
                float n3 = fmaf(-k31, c12, c22 + c32);
                c12 = n1; c22 = n2; c32 = n3;
            }
            {
                float n1 = fmaf(km,  yb.x, fmaf(-km,  bx1, bx1 + bx2));
                float n2 = fmaf(k2v, yb.x, fmaf(-k2v, bx1, bx2));
                float n3 = fmaf(k31, yb.x, fmaf(-k31, bx1, bx2 + bx3));
                bx1 = n1; bx2 = n2; bx3 = n3;
                float p1 = fmaf(km,  yb.y, fmaf(-km,  by1, by1 + by2));
                float p2 = fmaf(k2v, yb.y, fmaf(-k2v, by1, by2));
                float p3 = fmaf(k31, yb.y, fmaf(-k31, by1, by2 + by3));
                by1 = p1; by2 = p2; by3 = p3;
            }
        }
        float* r = s_cmp + tid * 12;
        r[0] = c11; r[1] = c21; r[2] = c31;
        r[3] = c12; r[4] = c22; r[5] = c32;
        r[6] = bx1; r[7] = bx2; r[8] = bx3;
        r[9] = by1; r[10] = by2; r[11] = by3;
    }
    __syncthreads();

    // -------- phase 2c: sequential combine across CH2 chunks --------
    if (tid == 0) {
        float m0 = s_pub[0], V0 = s_pub[1], PV0 = s_pub[2];
        float m1 = s_pub[3], V1 = s_pub[4], PV1 = s_pub[5];
        s_bnd[0] = m0; s_bnd[1] = V0; s_bnd[2] = PV0;
        s_bnd[3] = m1; s_bnd[4] = V1; s_bnd[5] = PV1;
        for (int k = 0; k < CH2; ++k) {
            const float* r = s_cmp + k * 12;
            float n0  = fmaf(r[0], m0, fmaf(r[3], V0, r[6]));
            float nV0 = fmaf(r[1], m0, fmaf(r[4], V0, r[7]));
            float nP0 = fmaf(r[2], m0, fmaf(r[5], V0, PV0 + r[8]));
            float n1  = fmaf(r[0], m1, fmaf(r[3], V1, r[9]));
            float nV1 = fmaf(r[1], m1, fmaf(r[4], V1, r[10]));
            float nP1 = fmaf(r[2], m1, fmaf(r[5], V1, PV1 + r[11]));
            m0 = n0; V0 = nV0; PV0 = nP0;
            m1 = n1; V1 = nV1; PV1 = nP1;
            float* b = s_bnd + (k + 1) * 6;
            b[0] = m0; b[1] = V0; b[2] = PV0;
            b[3] = m1; b[4] = V1; b[5] = PV1;
        }
    }
    __syncthreads();

    // -------- phase 2d: replay chunks for llq + final state --------
    if (tid < CH2) {
        const float* b = s_bnd + tid * 6;
        float m0 = b[0], V0 = b[1], PV0 = b[2];
        float m1 = b[3], V1 = b[4], PV1 = b[5];
        float mV0 = m0 + V0, mV1 = m1 + V1;
        float Pn0 = 0.f, Pn1 = 0.f, llq = 0.f;
        const int base = T1 + tid * WIN2;
        #pragma unroll 4
        for (int j = 0; j < WIN2; ++j) {
            float4 g  = Gp[base + j];
            float2 yb = ybp[base + j];
            float k12 = g.x + g.y;
            float km  = k12 + g.z;
            float Ib0 = yb.x - m0;
            float Ib1 = yb.y - m1;
            float vu0 = fmaf(g.y, Ib0, V0);
            float vu1 = fmaf(g.y, Ib1, V1);
            float mn0 = fmaf(km, Ib0, mV0);
            float mn1 = fmaf(km, Ib1, mV1);
            Pn0 = fmaf(k12, Ib0, PV0);
            Pn1 = fmaf(k12, Ib1, PV1);
            mV0 = mn0 + vu0;  mV1 = mn1 + vu1;
            PV0 = Pn0 + vu0;  PV1 = Pn1 + vu1;
            m0 = mn0;  m1 = mn1;
            V0 = vu0;  V1 = vu1;
            float ss = fmaf(Ib1, Ib1, Ib0 * Ib0);
            llq = fmaf(g.w, ss, llq);
        }
        s_llq[tid] = llq;
        if (tid == CH2 - 1) {
            s_pub[8]  = Pn0 - V0;  s_pub[9]  = Pn1 - V1;
            s_pub[10] = V0;        s_pub[11] = V1;
        }
    }

    // -------- wait sensor partials, reduce --------
    if (tid == 0) { while (*(volatile int*)&g_ctrC < NCHK) {} }
    __syncthreads();
    __threadfence();
    if (tid < OBS) {
        float accs = 0.0f;
        #pragma unroll 8
        for (int k = 0; k < NCHK; ++k)
            accs += g_accp[k * OBS + tid];
        s_acc[tid] = accs;
    }
    __syncthreads();

    if (tid == 0) {
        float atot = 0.0f;
        #pragma unroll 8
        for (int i = 0; i < OBS; ++i) atot += s_acc[i];
        float lsum = 0.0f;
        #pragma unroll 8
        for (int i = 0; i < 256; ++i) lsum += s_ld[i];
        float llq = s_pub[6];
        for (int i = 0; i < CH2; ++i) llq += s_llq[i];
        float x  = 1.0f / 4096.0f;
        float ea = x - XA, eb = x - XB, ec = x - XC;
        float L0 = eb * ec * IDA;
        float L1 = ea * ec * IDB;
        float L2 = ea * eb * IDC;
        float a = fmaf(L0, s_fit[0], fmaf(L1, s_fit[3], L2 * s_fit[6]));
        float d = fmaf(L0, s_fit[1], fmaf(L1, s_fit[4], L2 * s_fit[7]));
        float c = fmaf(L0, s_fit[2], fmaf(L1, s_fit[5], L2 * s_fit[8]));

        double ldS = -(double)lsum;
        double ldA = (double)(T_STEPS - 1) * log2((double)R)
                   + log2((double)R + (double)T_STEPS * (double)g0);
        double ld  = 63.0 * ldA + ldS + 6.0 * (double)T_STEPS;
        const double LN2    = 0.6931471805599453094;
        const double LOG2PI = 1.8378770664093454836;
        double quad = 0.5 * ((double)atot + (double)llq);
        double logp = -quad - ld * LN2 - 64.0 * (double)T_STEPS * LOG2PI;
        out[0] = (float)logp;
        out[1] = s_pub[8];  out[2] = s_pub[9];
        out[3] = s_pub[10]; out[4] = s_pub[11];
        out[5]  = a;   out[6]  = 0.f; out[7]  = d;   out[8]  = 0.f;
        out[9]  = 0.f; out[10] = a;   out[11] = 0.f; out[12] = d;
        out[13] = d;   out[14] = 0.f; out[15] = c;   out[16] = 0.f;
        out[17] = 0.f; out[18] = d;   out[19] = 0.f; out[20] = c;
        // reset barrier counters for the next graph replay (all arrivals done)
        g_ctrA = 0; g_ctrB = 0; g_ctrC = 0;
        __threadfence();
    }
}

extern "C" void kernel_launch(void* const* d_in, const int* in_sizes, int n_in,
                              void* d_out, int out_size) {
    const float* obs = (const float*)d_in[0];
    const float* lbs = (const float*)d_in[1];
    const float* lon = (const float*)d_in[2];
    const float* ltn = (const float*)d_in[3];
    float* out = (float*)d_out;
    (void)in_sizes; (void)n_in; (void)out_size;

    static bool attr_set = false;
    if (!attr_set) {
        cudaFuncSetAttribute(fused_kernel,
                             cudaFuncAttributeMaxDynamicSharedMemorySize,
                             SMEM_BYTES);
        attr_set = true;
    }
    fused_kernel<<<NCHK + 1, 256, SMEM_BYTES>>>(
        (const float4*)obs, lbs, lon, ltn, out);
}

// round 10
// speedup vs baseline: 4.4917x; 1.2204x over previous
#include <cuda_runtime.h>

// Kalman: NCV(4) + 128 static sensor biases, T=4096.
// Round 10: fully-overlapped single fused kernel (65 co-resident blocks).
//  - Workers 0..63: obs tile -> ybar chunk (release flag g_flagY[c]),
//    sensor chunk sums (ctrB barrier), prefix+replay partials (ctrC).
//  - Master block 64:
//      warp0: Riccati t<128 starts IMMEDIATELY (data independent),
//      warp1: mean chain, per-chunk smem-flag gated, lags warp0 by one
//             32-step window (named barrier 1),
//      warps2-7: stage ybar chunks into smem as worker flags land,
//      then: Lagrange gain fill (nodes tau=64/96/128), 124x32 affine scan,
//      shuffle reductions, output, counter/flag reset.

#define T_STEPS 4096
#define OBS 128
#define T1 128
#define WIN1 32
#define NW1 (T1 / WIN1)               // 4
#define WIN2 32
#define CH2 ((T_STEPS - T1) / WIN2)   // 124
#define NCHK 64                        // worker chunks (64 steps each)

__device__ float g_ybar[2 * T_STEPS];
__device__ float g_csum[NCHK * OBS];
__device__ float g_accp[NCHK * OBS];
__device__ int   g_flagY[NCHK];
__device__ int   g_ctrB, g_ctrC;

__device__ __forceinline__ float frcp(float x) {
    float r;
    asm("rcp.approx.f32 %0, %1;" : "=f"(r) : "f"(x));
    return r;
}
__device__ __forceinline__ int ldacq(const int* p) {
    int v;
    asm volatile("ld.acquire.gpu.s32 %0, [%1];" : "=r"(v) : "l"(p) : "memory");
    return v;
}
__device__ __forceinline__ void strel(int* p, int v) {
    asm volatile("st.release.gpu.s32 [%0], %1;" :: "l"(p), "r"(v) : "memory");
}

// ---- master smem layout (float offsets) ----
#define OFF_G    0            // float4[4096]  -> 16384
#define OFF_YB   16384        // float2[4096]  ->  8192
#define OFF_BND  24576        // (CH2+1)*6 = 750 -> 752
#define OFF_CMP  25328        // CH2*12 = 1488
#define OFF_RED  26816        // 32
#define OFF_FIT  26848        // 16
#define OFF_PUB  26864        // 16
#define OFF_YST  26880        // 64 (int flags)
#define SMEM_FLOATS 26944
#define SMEM_BYTES  (SMEM_FLOATS * 4)

// Lagrange nodes x = 1/tau at tau = 64, 96, 128
#define XA (1.0f / 64.0f)
#define XB (1.0f / 96.0f)
#define XC (1.0f / 128.0f)
#define IDA (  24576.0f)
#define IDB ( -73728.0f)
#define IDC (  49152.0f)

__global__ void __launch_bounds__(256, 1) fused_kernel(
    const float4* __restrict__ obs4,
    const float* __restrict__ lbs,
    const float* __restrict__ lon,
    const float* __restrict__ ltn,
    float* __restrict__ out)
{
    extern __shared__ float smem[];
    const int tid  = threadIdx.x;
    const int bid  = blockIdx.x;
    const int wid  = tid >> 5;
    const int lane = tid & 31;

    const float R  = expf(2.0f * lon[0]);
    const float q  = expf(2.0f * ltn[0]);
    const float g0 = expf(2.0f * lbs[0]);

    if (bid < NCHK) {
        // ==================== WORKER block: chunk bid ====================
        float* tile = smem;            // [64][128] floats (32 KB)
        float* yloc = smem + 8192;     // [2*64]
        float* itg  = smem + 8320;     // [64]
        float* iaT  = smem + 8384;     // [64]
        const int c  = bid;
        const int c0 = c * 64;

        // step 1: load tile + ybar for this chunk
        #pragma unroll
        for (int k = 0; k < 8; ++k) {
            int tl = wid * 8 + k;
            int t  = c0 + tl;
            float4 v = obs4[t * 32 + lane];
            ((float4*)tile)[tl * 32 + lane] = v;
            float s = (v.x + v.y) + (v.z + v.w);
            #pragma unroll
            for (int m = 8; m; m >>= 1)
                s += __shfl_xor_sync(0xffffffffu, s, m);
            s *= 0.015625f;
            if (lane == 0)  { yloc[2 * tl]     = s; g_ybar[2 * t]     = s; }
            if (lane == 16) { yloc[2 * tl + 1] = s; g_ybar[2 * t + 1] = s; }
        }
        if (tid < 64) {
            int t = c0 + tid;
            float den0 = fmaf((float)t, g0, R);
            float den1 = den0 + g0;
            itg[tid] = g0 * frcp(den0);
            iaT[tid] = den0 * frcp(den1) * frcp(R);
        }
        __syncthreads();
        if (tid == 0) strel(&g_flagY[c], 1);   // publish ybar chunk

        // step 2: per-sensor chunk sums
        if (tid < OBS) {
            const int comp = tid >> 6;
            float cs = 0.0f;
            #pragma unroll 8
            for (int i = 0; i < 64; ++i)
                cs += tile[i * OBS + tid] - yloc[2 * i + comp];
            g_csum[c * OBS + tid] = cs;
        }
        __syncthreads();
        if (tid == 0) {
            __threadfence();
            atomicAdd(&g_ctrB, 1);
            while (ldacq(&g_ctrB) < NCHK) {}
        }
        __syncthreads();

        // step 3: exclusive prefix + replay quad-form partial
        if (tid < OBS) {
            float S = 0.0f;
            #pragma unroll 8
            for (int k = 0; k < c; ++k)
                S += g_csum[k * OBS + tid];
            const int comp = tid >> 6;
            float acc = 0.0f;
            #pragma unroll 8
            for (int i = 0; i < 64; ++i) {
                float x  = tile[i * OBS + tid] - yloc[2 * i + comp];
                float rt = fmaf(-S, itg[i], x);
                S += x;
                acc = fmaf(iaT[i], rt * rt, acc);
            }
            g_accp[c * OBS + tid] = acc;
        }
        __syncthreads();
        if (tid == 0) { __threadfence(); atomicAdd(&g_ctrC, 1); }
        return;
    }

    // ======================= MASTER block =======================
    float4* Gp    = (float4*)(smem + OFF_G);
    float2* ybp   = (float2*)(smem + OFF_YB);
    float*  s_bnd = smem + OFF_BND;
    float*  s_cmp = smem + OFF_CMP;
    float*  s_red = smem + OFF_RED;
    float*  s_fit = smem + OFF_FIT;
    float*  s_pub = smem + OFF_PUB;
    volatile int* yst = (volatile int*)(smem + OFF_YST);

    const float q1 = q, q2 = 0.5f * q, q3 = q * (1.0f / 3.0f);
    const float R64 = R * 0.015625f;

    for (int i = tid; i < NCHK; i += 256) yst[i] = 0;
    __syncthreads();

    if (wid == 0) {
        // ------- Riccati chain, t < T1 (data independent, starts NOW) ----
        float a = 100.0f, c = 100.0f, d = 0.0f;
        float E = 0.0f, F = 0.0f, G = g0 * 0.015625f;
        float is = 1.0f;
        const bool st = (lane == 0);
        for (int w = 0; w < NW1; ++w) {
            const bool exact = (w == 0);
            #pragma unroll 8
            for (int j = 0; j < WIN1; ++j) {
                float cp = c + q1;
                float dp = (d + c) + q2;
                float ap = fmaf(2.0f, d, a) + (c + q3);
                float Ep = E + F;
                float u1 = ap + Ep;
                float u2 = dp + F;
                float u3 = Ep + G;
                float Sv = (u1 + u3) + R64;
                if (exact) is = frcp(Sv);
                else       is = is * fmaf(-Sv, is, 2.0f);
                float k1 = u1 * is, k2 = u2 * is, k3 = u3 * is;
                a = fmaf(-k1, u1, ap);
                d = fmaf(-k1, u2, dp);
                c = fmaf(-k2, u2, cp);
                E = fmaf(-k1, u3, Ep);
                F = fmaf(-k2, u3, F);
                G = fmaf(-k3, u3, G);
                if (st) Gp[w * WIN1 + j] = make_float4(k1, k2, k3, is);
            }
            if (st) {
                if (w == 1) { s_fit[0] = a; s_fit[1] = d; s_fit[2] = c; } // tau=64
                if (w == 2) { s_fit[3] = a; s_fit[4] = d; s_fit[5] = c; } // tau=96
                if (w == 3) { s_fit[6] = a; s_fit[7] = d; s_fit[8] = c; } // tau=128
            }
            asm volatile("bar.sync 1, 64;" ::: "memory");
        }
    } else if (wid == 1) {
        // ------- mean / loglik chain t < T1 (flag-gated, lags 1 window) --
        float m0 = 0.f, m1 = 0.f, V0 = 0.f, V1 = 0.f;
        float mV0 = 0.f, mV1 = 0.f, PV0 = 0.f, PV1 = 0.f;
        float llq = 0.f;
        for (int w = 0; w < NW1; ++w) {
            if ((w & 1) == 0) {                 // window pair needs chunk w/2
                while (yst[w >> 1] == 0) {}
                __threadfence_block();
            }
            asm volatile("bar.sync 1, 64;" ::: "memory");
            const int tb = w * WIN1;
            #pragma unroll 8
            for (int j = 0; j < WIN1; ++j) {
                float4 g  = Gp[tb + j];
                float2 yb = ybp[tb + j];
                float k12 = g.x + g.y;
                float km  = k12 + g.z;
                float Ib0 = yb.x - m0;
                float Ib1 = yb.y - m1;
                float vu0 = fmaf(g.y, Ib0, V0);
                float vu1 = fmaf(g.y, Ib1, V1);
                float mn0 = fmaf(km, Ib0, mV0);
                float mn1 = fmaf(km, Ib1, mV1);
                float Pn0 = fmaf(k12, Ib0, PV0);
                float Pn1 = fmaf(k12, Ib1, PV1);
                mV0 = mn0 + vu0;  mV1 = mn1 + vu1;
                PV0 = Pn0 + vu0;  PV1 = Pn1 + vu1;
                m0 = mn0;  m1 = mn1;
                V0 = vu0;  V1 = vu1;
                float ss = fmaf(Ib1, Ib1, Ib0 * Ib0);
                llq = fmaf(g.w, ss, llq);
            }
        }
        if (lane == 0) {
            s_pub[0] = m0; s_pub[1] = V0; s_pub[2] = PV0;
            s_pub[3] = m1; s_pub[4] = V1; s_pub[5] = PV1;
            s_pub[6] = llq;
        }
    } else {
        // ------- staging warps: copy ybar chunks to smem as flags land ---
        for (int c = wid - 2; c < NCHK; c += 6) {
            while (ldacq(&g_flagY[c]) == 0) {}
            float4 v = __ldcg(((const float4*)g_ybar) + c * 32 + lane);
            ((float4*)ybp)[c * 32 + lane] = v;
            __threadfence_block();
            if (lane == 0) yst[c] = 1;
        }
    }
    __syncthreads();

    // ------- phase 2a: fitted gains for t >= T1 + logdet partials -------
    {
        float4 fa = Gp[63], fb = Gp[95], fc = Gp[127];
        float ls = 0.0f;
        for (int t = tid; t < T_STEPS; t += 256) {
            float4 g;
            if (t >= T1) {
                float x  = frcp((float)(t + 1));
                float ea = x - XA, eb = x - XB, ec = x - XC;
                float L0 = eb * ec * IDA;
                float L1 = ea * ec * IDB;
                float L2 = ea * eb * IDC;
                g.x = fmaf(L0, fa.x, fmaf(L1, fb.x, L2 * fc.x));
                g.y = fmaf(L0, fa.y, fmaf(L1, fb.y, L2 * fc.y));
                g.z = fmaf(L0, fa.z, fmaf(L1, fb.z, L2 * fc.z));
                g.w = fmaf(L0, fa.w, fmaf(L1, fb.w, L2 * fc.w));
                Gp[t] = g;
            } else {
                g = Gp[t];
            }
            ls += __log2f(g.w);
        }
        #pragma unroll
        for (int m = 16; m; m >>= 1)
            ls += __shfl_xor_sync(0xffffffffu, ls, m);
        if (lane == 0) s_red[wid] = ls;          // s_red[0..7]
    }
    __syncthreads();

    // ---- phase 2b: compose per-chunk affine maps (s = (m, V, PV)) ----
    if (tid < CH2) {
        float c11 = 1.f, c21 = 0.f, c31 = 0.f;
        float c12 = 0.f, c22 = 1.f, c32 = 0.f;
        float bx1 = 0.f, bx2 = 0.f, bx3 = 0.f;
        float by1 = 0.f, by2 = 0.f, by3 = 0.f;
        const int base = T1 + tid * WIN2;
        #pragma unroll 4
        for (int j = 0; j < WIN2; ++j) {
            float4 g  = Gp[base + j];
            float2 yb = ybp[base + j];
            float k2v = g.y;
            float k12 = g.x + g.y;
            float km  = k12 + g.z;
            float k31 = k12 + k2v;
            {
                float n1 = fmaf(-km,  c11, c11 + c21);
                float n2 = fmaf(-k2v, c11, c21);
                float n3 = fmaf(-k31, c11, c21 + c31);
                c11 = n1; c21 = n2; c31 = n3;
            }
            {
                float n1 = fmaf(-km,  c12, c12 + c22);
                float n2 = fmaf(-k2v, c12, c22);
                float n3 = fmaf(-k31, c12, c22 + c32);
                c12 = n1; c22 = n2; c32 = n3;
            }
            {
                float n1 = fmaf(km,  yb.x, fmaf(-km,  bx1, bx1 + bx2));
                float n2 = fmaf(k2v, yb.x, fmaf(-k2v, bx1, bx2));
                float n3 = fmaf(k31, yb.x, fmaf(-k31, bx1, bx2 + bx3));
                bx1 = n1; bx2 = n2; bx3 = n3;
                float p1 = fmaf(km,  yb.y, fmaf(-km,  by1, by1 + by2));
                float p2 = fmaf(k2v, yb.y, fmaf(-k2v, by1, by2));
                float p3 = fmaf(k31, yb.y, fmaf(-k31, by1, by2 + by3));
                by1 = p1; by2 = p2; by3 = p3;
            }
        }
        float* r = s_cmp + tid * 12;
        r[0] = c11; r[1] = c21; r[2] = c31;
        r[3] = c12; r[4] = c22; r[5] = c32;
        r[6] = bx1; r[7] = bx2; r[8] = bx3;
        r[9] = by1; r[10] = by2; r[11] = by3;
    }
    __syncthreads();

    // -------- phase 2c: sequential combine across CH2 chunks --------
    if (tid == 0) {
        float m0 = s_pub[0], V0 = s_pub[1], PV0 = s_pub[2];
        float m1 = s_pub[3], V1 = s_pub[4], PV1 = s_pub[5];
        s_bnd[0] = m0; s_bnd[1] = V0; s_bnd[2] = PV0;
        s_bnd[3] = m1; s_bnd[4] = V1; s_bnd[5] = PV1;
        for (int k = 0; k < CH2; ++k) {
            const float* r = s_cmp + k * 12;
            float n0  = fmaf(r[0], m0, fmaf(r[3], V0, r[6]));
            float nV0 = fmaf(r[1], m0, fmaf(r[4], V0, r[7]));
            float nP0 = fmaf(r[2], m0, fmaf(r[5], V0, PV0 + r[8]));
            float n1  = fmaf(r[0], m1, fmaf(r[3], V1, r[9]));
            float nV1 = fmaf(r[1], m1, fmaf(r[4], V1, r[10]));
            float nP1 = fmaf(r[2], m1, fmaf(r[5], V1, PV1 + r[11]));
            m0 = n0; V0 = nV0; PV0 = nP0;
            m1 = n1; V1 = nV1; PV1 = nP1;
            float* b = s_bnd + (k + 1) * 6;
            b[0] = m0; b[1] = V0; b[2] = PV0;
            b[3] = m1; b[4] = V1; b[5] = PV1;
        }
    }
    __syncthreads();

    // -------- phase 2d: replay chunks for llq + final state --------
    float llq2d = 0.0f;
    if (tid < CH2) {
        const float* b = s_bnd + tid * 6;
        float m0 = b[0], V0 = b[1], PV0 = b[2];
        float m1 = b[3], V1 = b[4], PV1 = b[5];
        float mV0 = m0 + V0, mV1 = m1 + V1;
        float Pn0 = 0.f, Pn1 = 0.f;
        const int base = T1 + tid * WIN2;
        #pragma unroll 4
        for (int j = 0; j < WIN2; ++j) {
            float4 g  = Gp[base + j];
            float2 yb = ybp[base + j];
            float k12 = g.x + g.y;
            float km  = k12 + g.z;
            float Ib0 = yb.x - m0;
            float Ib1 = yb.y - m1;
            float vu0 = fmaf(g.y, Ib0, V0);
            float vu1 = fmaf(g.y, Ib1, V1);
            float mn0 = fmaf(km, Ib0, mV0);
            float mn1 = fmaf(km, Ib1, mV1);
            Pn0 = fmaf(k12, Ib0, PV0);
            Pn1 = fmaf(k12, Ib1, PV1);
            mV0 = mn0 + vu0;  mV1 = mn1 + vu1;
            PV0 = Pn0 + vu0;  PV1 = Pn1 + vu1;
            m0 = mn0;  m1 = mn1;
            V0 = vu0;  V1 = vu1;
            float ss = fmaf(Ib1, Ib1, Ib0 * Ib0);
            llq2d = fmaf(g.w, ss, llq2d);
        }
        if (tid == CH2 - 1) {
            s_pub[8]  = Pn0 - V0;  s_pub[9]  = Pn1 - V1;   // posterior pos
            s_pub[10] = V0;        s_pub[11] = V1;          // posterior vel
        }
    }
    #pragma unroll
    for (int m = 16; m; m >>= 1)
        llq2d += __shfl_xor_sync(0xffffffffu, llq2d, m);
    if (lane == 0) s_red[8 + wid] = llq2d;       // s_red[8..15]

    // -------- wait sensor partials, reduce --------
    if (tid == 0) { while (ldacq(&g_ctrC) < NCHK) {} }
    __syncthreads();
    {
        float accs = 0.0f;
        if (tid < OBS) {
            #pragma unroll 8
            for (int k = 0; k < NCHK; ++k)
                accs += g_accp[k * OBS + tid];
        }
        #pragma unroll
        for (int m = 16; m; m >>= 1)
            accs += __shfl_xor_sync(0xffffffffu, accs, m);
        if (lane == 0) s_red[16 + wid] = accs;   // s_red[16..23]
    }
    // reset global sync state for the next graph replay
    if (tid < NCHK) g_flagY[tid] = 0;
    if (tid == 200) g_ctrB = 0;
    if (tid == 201) g_ctrC = 0;
    __syncthreads();

    if (tid == 0) {
        float lsum = 0.f, llq = s_pub[6], atot = 0.f;
        #pragma unroll
        for (int i = 0; i < 8; ++i) {
            lsum += s_red[i];
            llq  += s_red[8 + i];
            atot += s_red[16 + i];
        }
        // covariance at T via Lagrange extrapolation to x = 1/4096
        float x  = 1.0f / 4096.0f;
        float ea = x - XA, eb = x - XB, ec = x - XC;
        float L0 = eb * ec * IDA;
        float L1 = ea * ec * IDB;
        float L2 = ea * eb * IDC;
        float a = fmaf(L0, s_fit[0], fmaf(L1, s_fit[3], L2 * s_fit[6]));
        float d = fmaf(L0, s_fit[1], fmaf(L1, s_fit[4], L2 * s_fit[7]));
        float c = fmaf(L0, s_fit[2], fmaf(L1, s_fit[5], L2 * s_fit[8]));

        double ldS = -(double)lsum;
        double ldA = (double)(T_STEPS - 1) * log2((double)R)
                   + log2((double)R + (double)T_STEPS * (double)g0);
        double ld  = 63.0 * ldA + ldS + 6.0 * (double)T_STEPS;
        const double LN2    = 0.6931471805599453094;
        const double LOG2PI = 1.8378770664093454836;
        double quad = 0.5 * ((double)atot + (double)llq);
        double logp = -quad - ld * LN2 - 64.0 * (double)T_STEPS * LOG2PI;
        out[0] = (float)logp;
        out[1] = s_pub[8];  out[2] = s_pub[9];
        out[3] = s_pub[10]; out[4] = s_pub[11];
        out[5]  = a;   out[6]  = 0.f; out[7]  = d;   out[8]  = 0.f;
        out[9]  = 0.f; out[10] = a;   out[11] = 0.f; out[12] = d;
        out[13] = d;   out[14] = 0.f; out[15] = c;   out[16] = 0.f;
        out[17] = 0.f; out[18] = d;   out[19] = 0.f; out[20] = c;
    }
}

extern "C" void kernel_launch(void* const* d_in, const int* in_sizes, int n_in,
                              void* d_out, int out_size) {
    const float* obs = (const float*)d_in[0];
    const float* lbs = (const float*)d_in[1];
    const float* lon = (const float*)d_in[2];
    const float* ltn = (const float*)d_in[3];
    float* out = (float*)d_out;
    (void)in_sizes; (void)n_in; (void)out_size;

    static bool attr_set = false;
    if (!attr_set) {
        cudaFuncSetAttribute(fused_kernel,
                             cudaFuncAttributeMaxDynamicSharedMemorySize,
                             SMEM_BYTES);
        attr_set = true;
    }
    fused_kernel<<<NCHK + 1, 256, SMEM_BYTES>>>(
        (const float4*)obs, lbs, lon, ltn, out);
}